// round 14
// baseline (speedup 1.0000x reference)
#include <cuda_runtime.h>

#define BB 256
#define TT 1024
#define DD 128
#define HH 256
#define CC 10
#define NBLK 128     // 32 unit-blocks x 4 batch-groups
#define NTHR 512

typedef unsigned long long u64;

// ---------------- device scratch ------------------------------------------------
__device__ float g_xT [(size_t)TT * DD * BB];        // [t][d][b]
__device__ float g_xg0[(size_t)TT * HH * BB * 4];    // [t][u][b][g]
__device__ float g_h0[2][HH * BB];                   // h0(t) in slot t&1
__device__ float g_h1[2][HH * BB];                   // h1(s) in slot s&1
__device__ float g_Wt_ih0[DD * HH * 4];              // [k][u][g]
__device__ float g_Wt_hh0[HH * HH * 4];
__device__ float g_Wt_ih1[HH * HH * 4];
__device__ float g_Wt_hh1[HH * HH * 4];
__device__ unsigned g_flags[4][32];                  // [batch-group][unit-block]
__device__ unsigned g_rel[4];

// ---------------- packed fp32x2 helpers ------------------------------------------
__device__ __forceinline__ u64 dup2(float w) {
    u64 r; asm("mov.b64 %0,{%1,%1};" : "=l"(r) : "f"(w)); return r;
}
__device__ __forceinline__ u64 pk2(float lo, float hi) {
    u64 r; asm("mov.b64 %0,{%1,%2};" : "=l"(r) : "f"(lo), "f"(hi)); return r;
}
__device__ __forceinline__ void pfma(u64& d, u64 a, u64 b) {
    asm("fma.rn.f32x2 %0,%1,%2,%0;" : "+l"(d) : "l"(a), "l"(b));
}
__device__ __forceinline__ u64 padd(u64 a, u64 b) {
    u64 r; asm("add.rn.f32x2 %0,%1,%2;" : "=l"(r) : "l"(a), "l"(b)); return r;
}
__device__ __forceinline__ float2 unpk(u64 v) {
    float2 f; asm("mov.b64 {%0,%1},%2;" : "=f"(f.x), "=f"(f.y) : "l"(v)); return f;
}
__device__ __forceinline__ float sigm(float x) { return 1.f / (1.f + __expf(-x)); }
__device__ __forceinline__ float tanh_(float x) { return 1.f - 2.f / (__expf(2.f * x) + 1.f); }

__device__ __forceinline__ void cpa8(void* smem_dst, const void* gsrc) {
    unsigned su = (unsigned)__cvta_generic_to_shared(smem_dst);
    asm volatile("cp.async.ca.shared.global [%0], [%1], 8;" :: "r"(su), "l"(gsrc) : "memory");
}
__device__ __forceinline__ void cpa_commit() {
    asm volatile("cp.async.commit_group;" ::: "memory");
}

// ---------------- init (every replay) ---------------------------------------------
__global__ void init_kernel() {
    int n = HH * BB;
    for (int i = blockIdx.x * blockDim.x + threadIdx.x; i < n; i += gridDim.x * blockDim.x) {
        g_h0[1][i] = 0.f;   // h0(-1)
        g_h1[1][i] = 0.f;   // h1(-1)
        g_h1[0][i] = 0.f;   // staged-but-unused at t=0; determinism
    }
    int idx = blockIdx.x * blockDim.x + threadIdx.x;
    if (idx < 128) g_flags[idx >> 5][idx & 31] = 0u;
    if (idx < 4) g_rel[idx] = 0u;
}

// ---------------- prep: x transpose + weight transpose ----------------------------
__global__ __launch_bounds__(256) void prep_kernel(const float* __restrict__ x,
                                                   const float* __restrict__ Wih0,
                                                   const float* __restrict__ Whh0,
                                                   const float* __restrict__ Wih1,
                                                   const float* __restrict__ Whh1) {
    const int bid = blockIdx.x;
    if (bid < 4096) {
        __shared__ float tile[64][33];
        const int t = bid >> 2, b0 = (bid & 3) * 64;
        for (int dc = 0; dc < DD; dc += 32) {
            for (int i = threadIdx.x; i < 64 * 32; i += 256) {
                int bi = i >> 5, di = i & 31;
                tile[bi][di] = x[((size_t)(b0 + bi) * TT + t) * DD + dc + di];
            }
            __syncthreads();
            for (int i = threadIdx.x; i < 64 * 32; i += 256) {
                int di = i >> 6, bi = i & 63;
                g_xT[((size_t)t * DD + dc + di) * BB + b0 + bi] = tile[bi][di];
            }
            __syncthreads();
        }
    } else {
        const int NI = DD * HH * 4, NH = HH * HH * 4;
        int idx = (bid - 4096) * 256 + threadIdx.x;
        if (idx < NI) {
            int g = idx & 3, u = (idx >> 2) & 255, k = idx >> 10;
            g_Wt_ih0[idx] = Wih0[(g * HH + u) * DD + k];
        } else if (idx < NI + 3 * NH) {
            int j = idx - NI, m = j / NH, r = j % NH;
            int g = r & 3, u = (r >> 2) & 255, k = r >> 10;
            if (m == 0)      g_Wt_hh0[r] = Whh0[(g * HH + u) * HH + k];
            else if (m == 1) g_Wt_ih1[r] = Wih1[(g * HH + u) * HH + k];
            else             g_Wt_hh1[r] = Whh1[(g * HH + u) * HH + k];
        }
    }
}

// ---------------- xg0 = x @ Wih0^T + b0, layout [t][u][b][g] -----------------------
__device__ __forceinline__ void gemm_2u(const float* __restrict__ A,
                                        const float* __restrict__ Wt,
                                        int K, int bofs, int u0, u64 acc[2][4][4]) {
#pragma unroll 2
    for (int k = 0; k < K; ++k) {
        ulonglong2 a0 = *(const ulonglong2*)(A + (size_t)k * BB + bofs);
        ulonglong2 a1 = *(const ulonglong2*)(A + (size_t)k * BB + bofs + 4);
        float4 w0 = *(const float4*)(Wt + ((size_t)k * HH + u0) * 4);
        float4 w1 = *(const float4*)(Wt + ((size_t)k * HH + u0 + 1) * 4);
        u64 a[4] = {a0.x, a0.y, a1.x, a1.y};
        float wv0[4] = {w0.x, w0.y, w0.z, w0.w};
        float wv1[4] = {w1.x, w1.y, w1.z, w1.w};
#pragma unroll
        for (int g = 0; g < 4; ++g) {
            u64 wp = dup2(wv0[g]);
#pragma unroll
            for (int p = 0; p < 4; ++p) pfma(acc[0][g][p], a[p], wp);
        }
#pragma unroll
        for (int g = 0; g < 4; ++g) {
            u64 wp = dup2(wv1[g]);
#pragma unroll
            for (int p = 0; p < 4; ++p) pfma(acc[1][g][p], a[p], wp);
        }
    }
}

__global__ __launch_bounds__(128) void xg0_kernel(const float* __restrict__ b0v) {
    const int bid = blockIdx.x;
    const int t = bid >> 5, sub = bid & 31;
    const int ub = sub >> 2, bb = sub & 3;
    const int m_t = threadIdx.x & 7, n_t = threadIdx.x >> 3;
    const int u0 = ub * 32 + n_t * 2;
    const int bofs = bb * 64 + m_t * 8;

    u64 acc[2][4][4];
#pragma unroll
    for (int uu = 0; uu < 2; ++uu)
#pragma unroll
        for (int g = 0; g < 4; ++g) {
            u64 bp = dup2(b0v[g * HH + u0 + uu]);
#pragma unroll
            for (int p = 0; p < 4; ++p) acc[uu][g][p] = bp;
        }
    gemm_2u(g_xT + (size_t)t * DD * BB, g_Wt_ih0, DD, bofs, u0, acc);

    float* X = g_xg0 + (size_t)t * HH * BB * 4;
#pragma unroll
    for (int uu = 0; uu < 2; ++uu)
#pragma unroll
        for (int p = 0; p < 4; ++p) {
            float2 gi = unpk(acc[uu][0][p]);
            float2 gf = unpk(acc[uu][1][p]);
            float2 gg = unpk(acc[uu][2][p]);
            float2 go = unpk(acc[uu][3][p]);
            float* dst = X + ((size_t)(u0 + uu) * BB + bofs + p * 2) * 4;
            *(float4*)dst       = make_float4(gi.x, gf.x, gg.x, go.x);
            *(float4*)(dst + 4) = make_float4(gi.y, gf.y, gg.y, go.y);
        }
}

// ---------------- grouped grid barrier (4 independent groups of 32 blocks) ---------
__device__ __forceinline__ void group_barrier(int bb, int ub, unsigned gen) {
    __threadfence();
    __syncthreads();
    if (threadIdx.x == 0) *(volatile unsigned*)&g_flags[bb][ub] = gen;
    if (ub == 0 && threadIdx.x < 32) {
        while (*(volatile unsigned*)&g_flags[bb][threadIdx.x] < gen) __nanosleep(20);
        __syncwarp();
        if (threadIdx.x == 0) {
            __threadfence();
            *(volatile unsigned*)&g_rel[bb] = gen;
        }
    }
    if (threadIdx.x == 0) {
        while (*(volatile unsigned*)&g_rel[bb] < gen) __nanosleep(20);
        __threadfence();
    }
    __syncthreads();
}

// ---------------- persistent LSTM ---------------------------------------------------
// smem: packed weights 3 x 8192 f32 (96KB) + a-ring 4 x 2048 f32 (32KB) = 128KB
#define SW_F32     (3 * 8192)
#define RING_F32   (4 * 2048)
#define SMEM_BYTES ((SW_F32 + RING_F32) * 4)

// stage one chunk (32 k-rows x 64 floats) into 2kk-packed layout:
// buf float4[kk2*32 + pair] = {a(kk0,b0), a(kk0,b1), a(kk1,b0), a(kk1,b1)}
__device__ __forceinline__ void stage_chunk(float* buf, const float* src, int tid) {
    const int kr = tid >> 4, j = tid & 15;          // k-row 0..31, 16B-col 0..15
    const int kk2 = kr >> 1, par = kr & 1;
    const float* g = src + (size_t)kr * BB + j * 4;
    float* d = buf + (kk2 * 32 + 2 * j) * 4 + par * 2;
    cpa8(d, g);            // (k, b4j), (k, b4j+1)  -> pair 2j
    cpa8(d + 4, g + 2);    // (k, b4j+2), (k,b4j+3) -> pair 2j+1
    cpa_commit();
}

__global__ __launch_bounds__(NTHR, 1) void lstm_persist(const float* __restrict__ b1v) {
    extern __shared__ float smemf[];
    float* sw0  = smemf;                 // hh0 packed: float4[(c*16+kk2)*16 + uloc*2 + gp]
    float* sw1  = smemf + 8192;          // ih1
    float* sw2  = smemf + 16384;         // hh1
    float* ring = smemf + SW_F32;        // 4 x 2048

    const int tid = threadIdx.x;
    const int gp = tid & 1;                     // gate-pair: 0={i,f}, 1={g,o}
    const int ul = (tid >> 1) & 3;
    const int pl = (tid >> 3) & 3;
    const int ug = (tid >> 5) & 1;
    const int pg = (tid >> 6) & 7;
    const int uloc = ug * 4 + ul;               // 0..7
    const int pair = pg * 4 + pl;               // 0..31
    const int ub = blockIdx.x >> 2, bb = blockIdx.x & 3;
    const int u = ub * 8 + uloc;
    const int bbase = bb * 64;
    const int aofs = bbase + pair * 2;

    // one-time packed weight load:
    // sw[m] float idx = ((c*16+kk2)*8 + uloc)*8 + gp*4 + jj ; k=(c*16+kk2)*2+(jj>>1), g=gp*2+(jj&1)
    {
        const float* srcs[3] = {g_Wt_hh0, g_Wt_ih1, g_Wt_hh1};
        float* dsts[3] = {sw0, sw1, sw2};
#pragma unroll
        for (int m = 0; m < 3; ++m) {
            const float* src = srcs[m] + ub * 32;
            float* dst = dsts[m];
            for (int idx = tid; idx < 8192; idx += NTHR) {
                int jj = idx & 3, gpp = (idx >> 2) & 1, ulc = (idx >> 3) & 7, k2 = idx >> 6;
                int k = k2 * 2 + (jj >> 1), g = gpp * 2 + (jj & 1);
                dst[idx] = src[(size_t)k * 1024 + ulc * 4 + g];
            }
        }
    }
    const u64 b1d = pk2(b1v[(2 * gp) * HH + u], b1v[(2 * gp + 1) * HH + u]);

    float c0[2] = {0.f, 0.f}, c1[2] = {0.f, 0.f};
    __syncthreads();

    // iteration t: L0 step t (t<1024) + L1 step t-1 (t>=1). 1025 iterations.
    for (int t = 0; t <= TT; ++t) {
        const float* h0p  = g_h0[(t + 1) & 1] + bbase;   // h0(t-1): feeds hh0 AND ih1
        const float* h1p2 = g_h1[t & 1]       + bbase;   // h1(t-2): feeds hh1

        // prefetch xg(t): this thread's gate-pair, 2 batches
        u64 xg_b0 = 0, xg_b1 = 0;
        if (t < TT) {
            const float* xg = g_xg0 + (((size_t)t * HH + u) * BB + aofs) * 4 + gp * 2;
            xg_b0 = __ldcg((const u64*)xg);
            xg_b1 = __ldcg((const u64*)(xg + 4));
        }

        stage_chunk(ring,        h0p, tid);
        stage_chunk(ring + 2048, h0p + 32 * BB, tid);

        u64 acc0[2] = {0, 0};   // L0 [batch]
        u64 acc1[2] = {0, 0};   // L1 [batch]

        for (int c = 0; c < 16; ++c) {
            if (c + 2 < 16) {
                const float* nsrc = (c + 2 < 8) ? (h0p + (size_t)(c + 2) * 32 * BB)
                                                : (h1p2 + (size_t)(c - 6) * 32 * BB);
                stage_chunk(ring + ((c + 2) & 3) * 2048, nsrc, tid);
                asm volatile("cp.async.wait_group 2;" ::: "memory");
            } else if (c + 1 < 16) {
                asm volatile("cp.async.wait_group 1;" ::: "memory");
            } else {
                asm volatile("cp.async.wait_group 0;" ::: "memory");
            }
            __syncthreads();
            const float* bf = ring + (c & 3) * 2048;
            if (c < 8) {
                const float* wA = sw0 + (size_t)c * 1024;
                const float* wB = sw1 + (size_t)c * 1024;
#pragma unroll
                for (int k2 = 0; k2 < 16; ++k2) {
                    float4 af = *(const float4*)(bf + (k2 * 32 + pair) * 4);
                    ulonglong2 wa = *(const ulonglong2*)(wA + (k2 * 8 + uloc) * 8 + gp * 4);
                    ulonglong2 wb = *(const ulonglong2*)(wB + (k2 * 8 + uloc) * 8 + gp * 4);
                    u64 a00 = dup2(af.x), a01 = dup2(af.y);
                    u64 a10 = dup2(af.z), a11 = dup2(af.w);
                    pfma(acc0[0], a00, wa.x); pfma(acc0[1], a01, wa.x);
                    pfma(acc0[0], a10, wa.y); pfma(acc0[1], a11, wa.y);
                    pfma(acc1[0], a00, wb.x); pfma(acc1[1], a01, wb.x);
                    pfma(acc1[0], a10, wb.y); pfma(acc1[1], a11, wb.y);
                }
            } else {
                const float* wC = sw2 + (size_t)(c - 8) * 1024;
#pragma unroll
                for (int k2 = 0; k2 < 16; ++k2) {
                    float4 af = *(const float4*)(bf + (k2 * 32 + pair) * 4);
                    ulonglong2 wc = *(const ulonglong2*)(wC + (k2 * 8 + uloc) * 8 + gp * 4);
                    u64 a00 = dup2(af.x), a01 = dup2(af.y);
                    u64 a10 = dup2(af.z), a11 = dup2(af.w);
                    pfma(acc1[0], a00, wc.x); pfma(acc1[1], a01, wc.x);
                    pfma(acc1[0], a10, wc.y); pfma(acc1[1], a11, wc.y);
                }
            }
        }

        // pointwise L0 -> h0(t): recombine gate-pairs via shfl with lane^1
        if (t < TT) {
            u64 s0 = padd(acc0[0], xg_b0);
            u64 s1 = padd(acc0[1], xg_b1);
            u64 p0 = __shfl_xor_sync(0xffffffffu, s0, 1);
            u64 p1 = __shfl_xor_sync(0xffffffffu, s1, 1);
            float2 if0 = unpk(gp ? p0 : s0), go0 = unpk(gp ? s0 : p0);
            float2 if1 = unpk(gp ? p1 : s1), go1 = unpk(gp ? s1 : p1);
            c0[0] = sigm(if0.y) * c0[0] + sigm(if0.x) * tanh_(go0.x);
            c0[1] = sigm(if1.y) * c0[1] + sigm(if1.x) * tanh_(go1.x);
            float h0a = sigm(go0.y) * tanh_(c0[0]);
            float h0b = sigm(go1.y) * tanh_(c0[1]);
            if (gp == 0)
                __stcg((float2*)(g_h0[t & 1] + (size_t)u * BB + aofs), make_float2(h0a, h0b));
        }
        // pointwise L1 step t-1 -> h1(t-1)
        if (t >= 1) {
            u64 s0 = padd(acc1[0], b1d);
            u64 s1 = padd(acc1[1], b1d);
            u64 p0 = __shfl_xor_sync(0xffffffffu, s0, 1);
            u64 p1 = __shfl_xor_sync(0xffffffffu, s1, 1);
            float2 if0 = unpk(gp ? p0 : s0), go0 = unpk(gp ? s0 : p0);
            float2 if1 = unpk(gp ? p1 : s1), go1 = unpk(gp ? s1 : p1);
            c1[0] = sigm(if0.y) * c1[0] + sigm(if0.x) * tanh_(go0.x);
            c1[1] = sigm(if1.y) * c1[1] + sigm(if1.x) * tanh_(go1.x);
            float h1a = sigm(go0.y) * tanh_(c1[0]);
            float h1b = sigm(go1.y) * tanh_(c1[1]);
            if (gp == 0)
                __stcg((float2*)(g_h1[(t + 1) & 1] + (size_t)u * BB + aofs), make_float2(h1a, h1b));
        }
        if (t < TT) group_barrier(bb, ub, (unsigned)(t + 1));
    }
}

// ---------------- dense + softmax (final h1(1023) = g_h1[1]) ------------------------
__global__ __launch_bounds__(256) void dense_softmax(const float* __restrict__ Wd,
                                                     const float* __restrict__ bd,
                                                     float* __restrict__ out) {
    const int b = threadIdx.x;
    const float* h = g_h1[1];
    float acc[CC];
#pragma unroll
    for (int c = 0; c < CC; ++c) acc[c] = bd[c];
    for (int u = 0; u < HH; ++u) {
        float hv = h[(size_t)u * BB + b];
#pragma unroll
        for (int c = 0; c < CC; ++c) acc[c] += hv * Wd[c * HH + u];
    }
    float mx = acc[0];
#pragma unroll
    for (int c = 1; c < CC; ++c) mx = fmaxf(mx, acc[c]);
    float sum = 0.f;
#pragma unroll
    for (int c = 0; c < CC; ++c) { acc[c] = expf(acc[c] - mx); sum += acc[c]; }
    float inv = 1.f / sum;
#pragma unroll
    for (int c = 0; c < CC; ++c) out[b * CC + c] = acc[c] * inv;
}

// ---------------- launch --------------------------------------------------------------
extern "C" void kernel_launch(void* const* d_in, const int* in_sizes, int n_in,
                              void* d_out, int out_size) {
    const float* x    = (const float*)d_in[0];
    const float* Wih0 = (const float*)d_in[1];
    const float* Whh0 = (const float*)d_in[2];
    const float* b0v  = (const float*)d_in[3];
    const float* Wih1 = (const float*)d_in[4];
    const float* Whh1 = (const float*)d_in[5];
    const float* b1v  = (const float*)d_in[6];
    const float* Wd   = (const float*)d_in[7];
    const float* bd   = (const float*)d_in[8];
    float* out = (float*)d_out;

    cudaFuncSetAttribute(lstm_persist, cudaFuncAttributeMaxDynamicSharedMemorySize, SMEM_BYTES);

    const int NW = DD * HH * 4 + 3 * HH * HH * 4;
    const int tw_blocks = (NW + 255) / 256;

    init_kernel<<<64, 256>>>();                                         // 0
    prep_kernel<<<4096 + tw_blocks, 256>>>(x, Wih0, Whh0, Wih1, Whh1);  // 1
    xg0_kernel<<<TT * 32, 128>>>(b0v);                                  // 2
    lstm_persist<<<NBLK, NTHR, SMEM_BYTES>>>(b1v);                      // 3
    dense_softmax<<<1, 256>>>(Wd, bd, out);                             // 4
}

// round 15
// speedup vs baseline: 1.2900x; 1.2900x over previous
#include <cuda_runtime.h>

#define BB 256
#define TT 1024
#define DD 128
#define HH 256
#define CC 10
#define NBLK 256     // 64 unit-blocks x 4 batch-groups
#define NTHR 128

typedef unsigned long long u64;

// ---------------- device scratch ------------------------------------------------
__device__ float g_xT [(size_t)TT * DD * BB];        // [t][d][b]
__device__ float g_xg0[(size_t)TT * HH * BB * 4];    // [t][u][b][g]
__device__ float g_h0[2][HH * BB];                   // h0(t) in slot t&1
__device__ float g_h1[2][HH * BB];                   // h1(s) in slot s&1
__device__ float g_Wt_ih0[DD * HH * 4];              // [k][u][g]
__device__ float g_Wt_hh0[HH * HH * 4];
__device__ float g_Wt_ih1[HH * HH * 4];
__device__ float g_Wt_hh1[HH * HH * 4];
__device__ unsigned g_flags[4][64];                  // [batch-group][unit-block]
__device__ unsigned g_rel[4];

// ---------------- packed fp32x2 helpers ------------------------------------------
__device__ __forceinline__ u64 dup2(float w) {
    u64 r; asm("mov.b64 %0,{%1,%1};" : "=l"(r) : "f"(w)); return r;
}
__device__ __forceinline__ u64 pk2(float lo, float hi) {
    u64 r; asm("mov.b64 %0,{%1,%2};" : "=l"(r) : "f"(lo), "f"(hi)); return r;
}
__device__ __forceinline__ void pfma(u64& d, u64 a, u64 b) {
    asm("fma.rn.f32x2 %0,%1,%2,%0;" : "+l"(d) : "l"(a), "l"(b));
}
__device__ __forceinline__ u64 padd(u64 a, u64 b) {
    u64 r; asm("add.rn.f32x2 %0,%1,%2;" : "=l"(r) : "l"(a), "l"(b)); return r;
}
__device__ __forceinline__ float2 unpk(u64 v) {
    float2 f; asm("mov.b64 {%0,%1},%2;" : "=f"(f.x), "=f"(f.y) : "l"(v)); return f;
}
__device__ __forceinline__ float sigm(float x) { return 1.f / (1.f + __expf(-x)); }
__device__ __forceinline__ float tanh_(float x) { return 1.f - 2.f / (__expf(2.f * x) + 1.f); }

__device__ __forceinline__ void cpa16(void* smem_dst, const void* gsrc) {
    unsigned su = (unsigned)__cvta_generic_to_shared(smem_dst);
    asm volatile("cp.async.cg.shared.global [%0], [%1], 16;" :: "r"(su), "l"(gsrc) : "memory");
}
__device__ __forceinline__ void cpa_commit() {
    asm volatile("cp.async.commit_group;" ::: "memory");
}

// ---------------- init (every replay) ---------------------------------------------
__global__ void init_kernel() {
    int n = HH * BB;
    for (int i = blockIdx.x * blockDim.x + threadIdx.x; i < n; i += gridDim.x * blockDim.x) {
        g_h0[1][i] = 0.f;   // h0(-1)
        g_h1[1][i] = 0.f;   // h1(-1)
        g_h1[0][i] = 0.f;   // staged-but-unused at t=0; determinism
    }
    int idx = blockIdx.x * blockDim.x + threadIdx.x;
    if (idx < 256) g_flags[idx >> 6][idx & 63] = 0u;
    if (idx < 4) g_rel[idx] = 0u;
}

// ---------------- prep: x transpose + weight transpose ----------------------------
__global__ __launch_bounds__(256) void prep_kernel(const float* __restrict__ x,
                                                   const float* __restrict__ Wih0,
                                                   const float* __restrict__ Whh0,
                                                   const float* __restrict__ Wih1,
                                                   const float* __restrict__ Whh1) {
    const int bid = blockIdx.x;
    if (bid < 4096) {
        __shared__ float tile[64][33];
        const int t = bid >> 2, b0 = (bid & 3) * 64;
        for (int dc = 0; dc < DD; dc += 32) {
            for (int i = threadIdx.x; i < 64 * 32; i += 256) {
                int bi = i >> 5, di = i & 31;
                tile[bi][di] = x[((size_t)(b0 + bi) * TT + t) * DD + dc + di];
            }
            __syncthreads();
            for (int i = threadIdx.x; i < 64 * 32; i += 256) {
                int di = i >> 6, bi = i & 63;
                g_xT[((size_t)t * DD + dc + di) * BB + b0 + bi] = tile[bi][di];
            }
            __syncthreads();
        }
    } else {
        const int NI = DD * HH * 4, NH = HH * HH * 4;
        int idx = (bid - 4096) * 256 + threadIdx.x;
        if (idx < NI) {
            int g = idx & 3, u = (idx >> 2) & 255, k = idx >> 10;
            g_Wt_ih0[idx] = Wih0[(g * HH + u) * DD + k];
        } else if (idx < NI + 3 * NH) {
            int j = idx - NI, m = j / NH, r = j % NH;
            int g = r & 3, u = (r >> 2) & 255, k = r >> 10;
            if (m == 0)      g_Wt_hh0[r] = Whh0[(g * HH + u) * HH + k];
            else if (m == 1) g_Wt_ih1[r] = Wih1[(g * HH + u) * HH + k];
            else             g_Wt_hh1[r] = Whh1[(g * HH + u) * HH + k];
        }
    }
}

// ---------------- xg0 = x @ Wih0^T + b0, layout [t][u][b][g] -----------------------
__device__ __forceinline__ void gemm_2u(const float* __restrict__ A,
                                        const float* __restrict__ Wt,
                                        int K, int bofs, int u0, u64 acc[2][4][4]) {
#pragma unroll 2
    for (int k = 0; k < K; ++k) {
        ulonglong2 a0 = *(const ulonglong2*)(A + (size_t)k * BB + bofs);
        ulonglong2 a1 = *(const ulonglong2*)(A + (size_t)k * BB + bofs + 4);
        float4 w0 = *(const float4*)(Wt + ((size_t)k * HH + u0) * 4);
        float4 w1 = *(const float4*)(Wt + ((size_t)k * HH + u0 + 1) * 4);
        u64 a[4] = {a0.x, a0.y, a1.x, a1.y};
        float wv0[4] = {w0.x, w0.y, w0.z, w0.w};
        float wv1[4] = {w1.x, w1.y, w1.z, w1.w};
#pragma unroll
        for (int g = 0; g < 4; ++g) {
            u64 wp = dup2(wv0[g]);
#pragma unroll
            for (int p = 0; p < 4; ++p) pfma(acc[0][g][p], a[p], wp);
        }
#pragma unroll
        for (int g = 0; g < 4; ++g) {
            u64 wp = dup2(wv1[g]);
#pragma unroll
            for (int p = 0; p < 4; ++p) pfma(acc[1][g][p], a[p], wp);
        }
    }
}

__global__ __launch_bounds__(128) void xg0_kernel(const float* __restrict__ b0v) {
    const int bid = blockIdx.x;
    const int t = bid >> 5, sub = bid & 31;
    const int ub = sub >> 2, bb = sub & 3;
    const int m_t = threadIdx.x & 7, n_t = threadIdx.x >> 3;
    const int u0 = ub * 32 + n_t * 2;
    const int bofs = bb * 64 + m_t * 8;

    u64 acc[2][4][4];
#pragma unroll
    for (int uu = 0; uu < 2; ++uu)
#pragma unroll
        for (int g = 0; g < 4; ++g) {
            u64 bp = dup2(b0v[g * HH + u0 + uu]);
#pragma unroll
            for (int p = 0; p < 4; ++p) acc[uu][g][p] = bp;
        }
    gemm_2u(g_xT + (size_t)t * DD * BB, g_Wt_ih0, DD, bofs, u0, acc);

    float* X = g_xg0 + (size_t)t * HH * BB * 4;
#pragma unroll
    for (int uu = 0; uu < 2; ++uu)
#pragma unroll
        for (int p = 0; p < 4; ++p) {
            float2 gi = unpk(acc[uu][0][p]);
            float2 gf = unpk(acc[uu][1][p]);
            float2 gg = unpk(acc[uu][2][p]);
            float2 go = unpk(acc[uu][3][p]);
            float* dst = X + ((size_t)(u0 + uu) * BB + bofs + p * 2) * 4;
            *(float4*)dst       = make_float4(gi.x, gf.x, gg.x, go.x);
            *(float4*)(dst + 4) = make_float4(gi.y, gf.y, gg.y, go.y);
        }
}

// ---------------- grouped grid barrier (4 groups of 64 blocks) ----------------------
__device__ __forceinline__ void group_barrier(int bb, int ub, unsigned gen) {
    __threadfence();
    __syncthreads();
    if (threadIdx.x == 0) *(volatile unsigned*)&g_flags[bb][ub] = gen;
    if (ub == 0 && threadIdx.x < 32) {
        while (*(volatile unsigned*)&g_flags[bb][threadIdx.x] < gen) __nanosleep(20);
        while (*(volatile unsigned*)&g_flags[bb][threadIdx.x + 32] < gen) __nanosleep(20);
        __syncwarp();
        if (threadIdx.x == 0) {
            __threadfence();
            *(volatile unsigned*)&g_rel[bb] = gen;
        }
    }
    if (threadIdx.x == 0) {
        while (*(volatile unsigned*)&g_rel[bb] < gen) __nanosleep(20);
        __threadfence();
    }
    __syncthreads();
}

// ---------------- persistent LSTM ---------------------------------------------------
// smem per block: weights 3 x 4096 f32 (48KB) + a-ring 4 x 2048 f32 (32KB) = 80KB
// -> 2 blocks co-resident per SM (the point of this round)
#define SW_F32     (3 * 4096)
#define RING_F32   (4 * 2048)
#define SMEM_BYTES ((SW_F32 + RING_F32) * 4)

// stage one 8KB chunk (32 k-rows x 64 floats) via cp.async, 128 threads x 64B
__device__ __forceinline__ void stage_chunk(float* buf, const float* src, int tid) {
#pragma unroll
    for (int i = 0; i < 4; ++i) {
        int s = tid + i * 128;                 // 512 x 16B segments
        int row = s >> 4, col = (s & 15) * 4;
        cpa16(buf + row * 64 + col, src + (size_t)row * BB + col);
    }
    cpa_commit();
}

// one 32-k chunk, one weight matrix: acc[b][gp] += dup(a_b) * w{gp}
__device__ __forceinline__ void mma_chunk(const float* __restrict__ bf,
                                          const float* __restrict__ wb,
                                          int pair, int uloc, u64 acc[2][2]) {
#pragma unroll 8
    for (int kk = 0; kk < 32; ++kk) {
        float2 av = *(const float2*)(bf + kk * 64 + pair * 2);
        u64 a0 = dup2(av.x), a1 = dup2(av.y);
        ulonglong2 wA = *(const ulonglong2*)(wb + kk * 16 + uloc * 4);
        pfma(acc[0][0], a0, wA.x); pfma(acc[0][1], a0, wA.y);
        pfma(acc[1][0], a1, wA.x); pfma(acc[1][1], a1, wA.y);
    }
}

__global__ __launch_bounds__(NTHR, 2) void lstm_persist(const float* __restrict__ b1v) {
    extern __shared__ float smemf[];
    float* sw0  = smemf;                 // hh0: [chunk][kk][uloc][g], 4096 f32
    float* sw1  = smemf + 4096;          // ih1
    float* sw2  = smemf + 8192;          // hh1
    float* ring = smemf + SW_F32;        // 4 x 2048

    const int tid  = threadIdx.x;
    const int warp = tid >> 5, lane = tid & 31;
    const int pl = lane & 15, ul = lane >> 4;
    const int pg = warp & 1,  ug = warp >> 1;           // ug 0..1
    const int pair = pg * 16 + pl;          // 0..31
    const int uloc = ug * 2 + ul;           // 0..3
    const int ub = blockIdx.x >> 2, bb = blockIdx.x & 3;   // ub 0..63
    const int u = ub * 4 + uloc;
    const int bbase = bb * 64;
    const int aofs = bbase + pair * 2;

    // one-time weight load: sw[(k*4+uloc)*4+g] = W[k][ub*4+uloc][g]
    {
        const float* srcs[3] = {g_Wt_hh0, g_Wt_ih1, g_Wt_hh1};
        float* dsts[3] = {sw0, sw1, sw2};
#pragma unroll
        for (int m = 0; m < 3; ++m) {
            const float* src = srcs[m] + ub * 16;
            float* dst = dsts[m];
            for (int idx = tid; idx < 4096; idx += NTHR)
                dst[idx] = src[(size_t)(idx >> 4) * 1024 + (idx & 15)];
        }
    }
    u64 b1d[2];
    b1d[0] = pk2(b1v[0 * HH + u], b1v[1 * HH + u]);
    b1d[1] = pk2(b1v[2 * HH + u], b1v[3 * HH + u]);

    float c0[2] = {0.f, 0.f}, c1[2] = {0.f, 0.f};
    __syncthreads();

    for (int t = 0; t <= TT; ++t) {
        const float* h0p  = g_h0[(t + 1) & 1] + bbase;   // h0(t-1): feeds hh0 AND ih1
        const float* h1p2 = g_h1[t & 1]       + bbase;   // h1(t-2): feeds hh1

        // prefetch xg(t) as gate-pairs (layout [u][b][g])
        u64 xgr[2][2];
        if (t < TT) {
            const float* xg = g_xg0 + (((size_t)t * HH + u) * BB + aofs) * 4;
            float4 x0 = __ldcg((const float4*)xg);
            float4 x1 = __ldcg((const float4*)(xg + 4));
            xgr[0][0] = pk2(x0.x, x0.y); xgr[0][1] = pk2(x0.z, x0.w);
            xgr[1][0] = pk2(x1.x, x1.y); xgr[1][1] = pk2(x1.z, x1.w);
        }

        // prologue: 2 chunks in flight (4-deep ring, distance 2 -> no WAR hazard)
        stage_chunk(ring,        h0p, tid);
        stage_chunk(ring + 2048, h0p + 32 * BB, tid);

        u64 acc0[2][2] = {{0, 0}, {0, 0}};   // [batch][gate-pair] L0
        u64 acc1[2][2] = {{0, 0}, {0, 0}};   // L1

        for (int c = 0; c < 16; ++c) {
            if (c + 2 < 16) {
                const float* nsrc = (c + 2 < 8) ? (h0p + (size_t)(c + 2) * 32 * BB)
                                                : (h1p2 + (size_t)(c - 6) * 32 * BB);
                stage_chunk(ring + ((c + 2) & 3) * 2048, nsrc, tid);
                asm volatile("cp.async.wait_group 2;" ::: "memory");
            } else if (c + 1 < 16) {
                asm volatile("cp.async.wait_group 1;" ::: "memory");
            } else {
                asm volatile("cp.async.wait_group 0;" ::: "memory");
            }
            __syncthreads();
            const float* bf = ring + (c & 3) * 2048;
            if (c < 8) {
                mma_chunk(bf, sw0 + (size_t)c * 512, pair, uloc, acc0);
                mma_chunk(bf, sw1 + (size_t)c * 512, pair, uloc, acc1);
            } else {
                mma_chunk(bf, sw2 + (size_t)(c - 8) * 512, pair, uloc, acc1);
            }
        }

        // pointwise L0 -> h0(t)
        if (t < TT) {
            float hv[2];
#pragma unroll
            for (int b = 0; b < 2; ++b) {
                float2 if_ = unpk(padd(acc0[b][0], xgr[b][0]));
                float2 go  = unpk(padd(acc0[b][1], xgr[b][1]));
                c0[b] = sigm(if_.y) * c0[b] + sigm(if_.x) * tanh_(go.x);
                hv[b] = sigm(go.y) * tanh_(c0[b]);
            }
            __stcg((float2*)(g_h0[t & 1] + (size_t)u * BB + aofs), make_float2(hv[0], hv[1]));
        }
        // pointwise L1 step t-1 -> h1(t-1)
        if (t >= 1) {
            float hv[2];
#pragma unroll
            for (int b = 0; b < 2; ++b) {
                float2 if_ = unpk(padd(acc1[b][0], b1d[0]));
                float2 go  = unpk(padd(acc1[b][1], b1d[1]));
                c1[b] = sigm(if_.y) * c1[b] + sigm(if_.x) * tanh_(go.x);
                hv[b] = sigm(go.y) * tanh_(c1[b]);
            }
            __stcg((float2*)(g_h1[(t + 1) & 1] + (size_t)u * BB + aofs), make_float2(hv[0], hv[1]));
        }
        if (t < TT) group_barrier(bb, ub, (unsigned)(t + 1));
    }
}

// ---------------- dense + softmax (final h1(1023) = g_h1[1]) ------------------------
__global__ __launch_bounds__(256) void dense_softmax(const float* __restrict__ Wd,
                                                     const float* __restrict__ bd,
                                                     float* __restrict__ out) {
    const int b = threadIdx.x;
    const float* h = g_h1[1];
    float acc[CC];
#pragma unroll
    for (int c = 0; c < CC; ++c) acc[c] = bd[c];
    for (int u = 0; u < HH; ++u) {
        float hv = h[(size_t)u * BB + b];
#pragma unroll
        for (int c = 0; c < CC; ++c) acc[c] += hv * Wd[c * HH + u];
    }
    float mx = acc[0];
#pragma unroll
    for (int c = 1; c < CC; ++c) mx = fmaxf(mx, acc[c]);
    float sum = 0.f;
#pragma unroll
    for (int c = 0; c < CC; ++c) { acc[c] = expf(acc[c] - mx); sum += acc[c]; }
    float inv = 1.f / sum;
#pragma unroll
    for (int c = 0; c < CC; ++c) out[b * CC + c] = acc[c] * inv;
}

// ---------------- launch --------------------------------------------------------------
extern "C" void kernel_launch(void* const* d_in, const int* in_sizes, int n_in,
                              void* d_out, int out_size) {
    const float* x    = (const float*)d_in[0];
    const float* Wih0 = (const float*)d_in[1];
    const float* Whh0 = (const float*)d_in[2];
    const float* b0v  = (const float*)d_in[3];
    const float* Wih1 = (const float*)d_in[4];
    const float* Whh1 = (const float*)d_in[5];
    const float* b1v  = (const float*)d_in[6];
    const float* Wd   = (const float*)d_in[7];
    const float* bd   = (const float*)d_in[8];
    float* out = (float*)d_out;

    cudaFuncSetAttribute(lstm_persist, cudaFuncAttributeMaxDynamicSharedMemorySize, SMEM_BYTES);

    const int NW = DD * HH * 4 + 3 * HH * HH * 4;
    const int tw_blocks = (NW + 255) / 256;

    init_kernel<<<64, 256>>>();                                         // 0
    prep_kernel<<<4096 + tw_blocks, 256>>>(x, Wih0, Whh0, Wih1, Whh1);  // 1
    xg0_kernel<<<TT * 32, 128>>>(b0v);                                  // 2
    lstm_persist<<<NBLK, NTHR, SMEM_BYTES>>>(b1v);                      // 3
    dense_softmax<<<1, 256>>>(Wd, bd, out);                             // 4
}